// round 5
// baseline (speedup 1.0000x reference)
#include <cuda_runtime.h>
#include <cuda_fp16.h>
#include <cstdint>

#define NB 4
#define NH 8
#define NT 2048
#define DH 32
#define NC 256
#define SCALE 0.17677669529663687f
#define L2E   1.4426950408889634f

static __device__ __half g_q[(size_t)NB*NH*NT*DH];
static __device__ __half g_k[(size_t)NB*NH*NT*DH];
static __device__ __half g_v[(size_t)NB*NH*NT*DH];
static __device__ float  g_x[(size_t)NB*NT*NC];
static __device__ float  g_icm[NB*NT];
static __device__ float  g_cmp[(size_t)NB*64*NT];
static __device__ __half g_mh[(size_t)NB*NT*NT];

__device__ __forceinline__ float fast_ex2(float x){
    float y; asm("ex2.approx.ftz.f32 %0, %1;" : "=f"(y) : "f"(x)); return y;
}
__device__ __forceinline__ void mma16816(float* c, const unsigned* a, unsigned b0, unsigned b1){
    asm volatile("mma.sync.aligned.m16n8k16.row.col.f32.f16.f16.f32 "
        "{%0,%1,%2,%3},{%4,%5,%6,%7},{%8,%9},{%0,%1,%2,%3};"
        : "+f"(c[0]), "+f"(c[1]), "+f"(c[2]), "+f"(c[3])
        : "r"(a[0]), "r"(a[1]), "r"(a[2]), "r"(a[3]), "r"(b0), "r"(b1));
}
__device__ __forceinline__ unsigned pack_half2(float x, float y){
    __half2 h = __floats2half2_rn(x, y); return *reinterpret_cast<unsigned*>(&h);
}
__device__ __forceinline__ uint32_t s2u(const void* p){
    return (uint32_t)__cvta_generic_to_shared(p);
}
__device__ __forceinline__ void ldsm_x4(unsigned* a, uint32_t addr){
    asm volatile("ldmatrix.sync.aligned.m8n8.x4.shared.b16 {%0,%1,%2,%3}, [%4];"
        : "=r"(a[0]),"=r"(a[1]),"=r"(a[2]),"=r"(a[3]) : "r"(addr));
}
__device__ __forceinline__ void ldsm_x2(unsigned& b0, unsigned& b1, uint32_t addr){
    asm volatile("ldmatrix.sync.aligned.m8n8.x2.shared.b16 {%0,%1}, [%2];"
        : "=r"(b0),"=r"(b1) : "r"(addr));
}
__device__ __forceinline__ void ldsm_x2t(unsigned& b0, unsigned& b1, uint32_t addr){
    asm volatile("ldmatrix.sync.aligned.m8n8.x2.trans.shared.b16 {%0,%1}, [%2];"
        : "=r"(b0),"=r"(b1) : "r"(addr));
}

// ---------------- mask prep (parallel) ----------------
__global__ void colmax_part(const float* __restrict__ mask){
    int b = blockIdx.x, s = blockIdx.y;
    const float* base = mask + (size_t)b*NT*NT + (size_t)s*32*NT;
#pragma unroll
    for (int qi = 0; qi < 8; qi++){
        int q = qi*256 + threadIdx.x;
        float mx = 0.f;
#pragma unroll
        for (int k = 0; k < 32; k++) mx = fmaxf(mx, base[(size_t)k*NT + q]);
        g_cmp[((size_t)b*64 + s)*NT + q] = mx;
    }
}
__global__ void colmax_fin(){
    int i = blockIdx.x*256 + threadIdx.x;
    int b = i >> 11, q = i & (NT-1);
    float mx = 0.f;
#pragma unroll
    for (int s = 0; s < 64; s++) mx = fmaxf(mx, g_cmp[((size_t)b*64 + s)*NT + q]);
    g_icm[i] = 1.0f / mx;
}

__global__ void mask_prep_kernel(const float* __restrict__ mask){
    __shared__ float t[32][33];
    int b = blockIdx.z;
    int k0 = blockIdx.x * 32, q0 = blockIdx.y * 32;
    int tx = threadIdx.x & 31, ty = threadIdx.x >> 5;
#pragma unroll
    for (int i = 0; i < 4; i++)
        t[ty + i*8][tx] = mask[(size_t)b*NT*NT + (size_t)(k0 + ty + i*8)*NT + q0 + tx];
    __syncthreads();
#pragma unroll
    for (int i = 0; i < 4; i++){
        int q = q0 + ty + i*8;
        g_mh[((size_t)b*NT + q)*NT + k0 + tx] =
            __float2half(t[tx][ty + i*8] * g_icm[b*NT + q]);
    }
}

// ---------------- GEMM: OUT[8192,256] = X @ W^T + bias ----------------
template<bool OUTPROJ>
__global__ __launch_bounds__(256) void gemm_kernel(
    const float* __restrict__ Xin,
    const float* __restrict__ Wa, const float* __restrict__ ba,
    const float* __restrict__ Wb, const float* __restrict__ bb_,
    const float* __restrict__ Wc, const float* __restrict__ bc,
    const float* __restrict__ resid, float* __restrict__ outF)
{
    __shared__ __half sA[128*72];
    __shared__ __half sB[64*72];
    const float* X = OUTPROJ ? (const float*)g_x : Xin;   // device-side symbol!
    const int m0 = blockIdx.x * 128, j0 = blockIdx.y * 64;
    const int pz = blockIdx.z;
    const float* W    = (pz == 0) ? Wa : (pz == 1) ? Wb : Wc;
    const float* bias = (pz == 0) ? ba : (pz == 1) ? bb_ : bc;
    __half* outH      = (pz == 0) ? g_q : (pz == 1) ? g_k : g_v;
    const float osc   = (!OUTPROJ && pz == 0) ? SCALE : 1.0f;

    const int tid = threadIdx.x, lane = tid & 31, wid = tid >> 5;
    const int wm = wid >> 1, wn = wid & 1;

    float acc[2][4][4];
#pragma unroll
    for (int m = 0; m < 2; m++)
#pragma unroll
        for (int nt = 0; nt < 4; nt++)
#pragma unroll
            for (int i = 0; i < 4; i++) acc[m][nt][i] = 0.f;

    for (int k0 = 0; k0 < NC; k0 += 64){
        __syncthreads();
#pragma unroll
        for (int i = 0; i < 8; i++){
            int e = tid + i*256, r = e >> 4, c4 = e & 15;
            float4 v = *(const float4*)&X[(size_t)(m0 + r)*NC + k0 + c4*4];
            *(__half2*)&sA[r*72 + c4*4]     = __floats2half2_rn(v.x, v.y);
            *(__half2*)&sA[r*72 + c4*4 + 2] = __floats2half2_rn(v.z, v.w);
        }
#pragma unroll
        for (int i = 0; i < 4; i++){
            int e = tid + i*256, r = e >> 4, c4 = e & 15;
            float4 v = *(const float4*)&W[(size_t)(j0 + r)*NC + k0 + c4*4];
            *(__half2*)&sB[r*72 + c4*4]     = __floats2half2_rn(v.x, v.y);
            *(__half2*)&sB[r*72 + c4*4 + 2] = __floats2half2_rn(v.z, v.w);
        }
        __syncthreads();
#pragma unroll
        for (int kk = 0; kk < 4; kk++){
            int dc = kk*16 + 2*(lane & 3);
            unsigned a[2][4], bb[4][2];
#pragma unroll
            for (int m = 0; m < 2; m++){
                int r = wm*32 + m*16 + (lane >> 2);
                a[m][0] = *(const unsigned*)&sA[r*72 + dc];
                a[m][1] = *(const unsigned*)&sA[(r + 8)*72 + dc];
                a[m][2] = *(const unsigned*)&sA[r*72 + dc + 8];
                a[m][3] = *(const unsigned*)&sA[(r + 8)*72 + dc + 8];
            }
#pragma unroll
            for (int nt = 0; nt < 4; nt++){
                int rj = wn*32 + nt*8 + (lane >> 2);
                bb[nt][0] = *(const unsigned*)&sB[rj*72 + dc];
                bb[nt][1] = *(const unsigned*)&sB[rj*72 + dc + 8];
            }
#pragma unroll
            for (int m = 0; m < 2; m++)
#pragma unroll
                for (int nt = 0; nt < 4; nt++)
                    mma16816(acc[m][nt], a[m], bb[nt][0], bb[nt][1]);
        }
    }

#pragma unroll
    for (int m = 0; m < 2; m++)
#pragma unroll
        for (int nt = 0; nt < 4; nt++){
            int row = m0 + wm*32 + m*16 + (lane >> 2);
            int col = j0 + wn*32 + nt*8 + 2*(lane & 3);
            float b0f = bias[col], b1f = bias[col + 1];
#pragma unroll
            for (int rg = 0; rg < 2; rg++){
                int rr = row + rg*8;
                if (OUTPROJ){
                    float2 o;
                    o.x = acc[m][nt][rg*2 + 0] + b0f + resid[(size_t)rr*NC + col];
                    o.y = acc[m][nt][rg*2 + 1] + b1f + resid[(size_t)rr*NC + col + 1];
                    *(float2*)&outF[(size_t)rr*NC + col] = o;
                } else {
                    int bb2 = rr >> 11, n = rr & (NT-1);
                    int hh = col >> 5, dd = col & 31;
                    size_t addr = ((size_t)(bb2*NH + hh)*NT + n)*DH + dd;
                    *(__half2*)&outH[addr] =
                        __floats2half2_rn((acc[m][nt][rg*2 + 0] + b0f)*osc,
                                          (acc[m][nt][rg*2 + 1] + b1f)*osc);
                }
            }
        }
}

// ---------------- fused attention (TQ=16, 2 CTAs/SM) ----------------
#define TQ 16
#define CHUNK 512
#define SS_STRIDE 2056
#define SK_STRIDE 40
#define OFF_S   0
#define SZ_S    (TQ*SS_STRIDE*2)             // 65792
#define OFF_KV  (SZ_S)
#define SZ_KV   (CHUNK*SK_STRIDE*2)          // 40960
#define OFF_Q   (OFF_KV + SZ_KV)             // 106752
#define SZ_Q    (TQ*SK_STRIDE*2)             // 1280
#define OFF_ST  (OFF_Q + SZ_Q)               // 108032
#define SMEM_ATTN (OFF_ST + TQ*4)            // 108096

__global__ __launch_bounds__(256, 2) void attn_kernel(float* __restrict__ attn_out)
{
    extern __shared__ char smem[];
    __half* sS  = (__half*)(smem + OFF_S);
    __half* sKV = (__half*)(smem + OFF_KV);
    __half* sQ  = (__half*)(smem + OFF_Q);
    float*  sInv = (float*)(smem + OFF_ST);

    const int h = blockIdx.x, qt = blockIdx.y, b = blockIdx.z;
    const int bh = b*NH + h;
    const int q0 = qt*TQ;
    const int tid = threadIdx.x, lane = tid & 31, wid = tid >> 5;

    const __half* gQ = g_q + ((size_t)bh*NT + q0)*DH;
    const __half* gK = g_k + (size_t)bh*NT*DH;
    const __half* gV = g_v + (size_t)bh*NT*DH;

    if (tid < 64){
        int r = tid >> 2, seg = tid & 3;
        *(uint4*)&sQ[r*SK_STRIDE + seg*8] = *(const uint4*)&gQ[r*DH + seg*8];
    }

    // ---- Phase 1: S = Q K^T (Q pre-scaled) -> smem half ----
    unsigned aq[2][4];
    for (int ct = 0; ct < NT/CHUNK; ct++){
        __syncthreads();
#pragma unroll
        for (int i = 0; i < 8; i++){
            int e = tid + i*256, r = e >> 2, seg = e & 3;
            *(uint4*)&sKV[r*SK_STRIDE + seg*8] =
                *(const uint4*)&gK[(size_t)(ct*CHUNK + r)*DH + seg*8];
        }
        __syncthreads();
        if (ct == 0){
            uint32_t qa0 = s2u(&sQ[(lane & 15)*SK_STRIDE + 8*(lane >> 4)]);
            ldsm_x4(aq[0], qa0);
            ldsm_x4(aq[1], qa0 + 32);   // k 16..31
        }
#pragma unroll
        for (int nt = 0; nt < 8; nt++){
            int t0 = wid*64 + nt*8;
            uint32_t ba = s2u(&sKV[(t0 + (lane & 7))*SK_STRIDE + 8*((lane >> 3) & 1)]);
            float c[4] = {0.f,0.f,0.f,0.f};
            unsigned b0, b1;
            ldsm_x2(b0, b1, ba);
            mma16816(c, aq[0], b0, b1);
            ldsm_x2(b0, b1, ba + 32);
            mma16816(c, aq[1], b0, b1);
            int gc = ct*CHUNK + t0 + 2*(lane & 3);
            int r0 = lane >> 2;
            *(__half2*)&sS[(r0    )*SS_STRIDE + gc] = __floats2half2_rn(c[0], c[1]);
            *(__half2*)&sS[(r0 + 8)*SS_STRIDE + gc] = __floats2half2_rn(c[2], c[3]);
        }
    }
    __syncthreads();

    // ---- Phase 2: exp in place + row sum (no max shift; |s| small) ----
#pragma unroll
    for (int rr = 0; rr < 2; rr++){
        int row = wid*2 + rr;
        uint2* sr8 = (uint2*)&sS[row*SS_STRIDE];   // 4 halves per uint2
        float sum = 0.f;
#pragma unroll 4
        for (int j = lane; j < NT/4; j += 32){
            uint2 u = sr8[j];
            float2 f0 = __half22float2(*(__half2*)&u.x);
            float2 f1 = __half22float2(*(__half2*)&u.y);
            float e00 = fast_ex2(f0.x*L2E), e01 = fast_ex2(f0.y*L2E);
            float e10 = fast_ex2(f1.x*L2E), e11 = fast_ex2(f1.y*L2E);
            sum += (e00 + e01) + (e10 + e11);
            u.x = pack_half2(e00, e01);
            u.y = pack_half2(e10, e11);
            sr8[j] = u;
        }
#pragma unroll
        for (int o = 16; o > 0; o >>= 1) sum += __shfl_xor_sync(0xffffffffu, sum, o);
        if (lane == 0) sInv[row] = 1.0f / sum;
    }
    __syncthreads();

    // ---- Phase 3: attn_vis + masked AV (exp precomputed in sS) ----
    float acc[4][4];
#pragma unroll
    for (int nt = 0; nt < 4; nt++)
#pragma unroll
        for (int i = 0; i < 4; i++) acc[nt][i] = 0.f;

    const int r_lo = lane >> 2, r_hi = r_lo + 8;
    const float invA = sInv[r_lo], invB = sInv[r_hi];
    const __half2 invA2 = __float2half2_rn(invA);
    const __half2 invB2 = __float2half2_rn(invB);
    const __half* mrowA = g_mh + ((size_t)b*NT + q0 + r_lo)*NT;
    const __half* mrowB = g_mh + ((size_t)b*NT + q0 + r_hi)*NT;
    float* outA = attn_out + ((size_t)bh*NT + q0 + r_lo)*NT;
    float* outB = attn_out + ((size_t)bh*NT + q0 + r_hi)*NT;
    const __half* srowA = &sS[r_lo*SS_STRIDE];
    const __half* srowB = &sS[r_hi*SS_STRIDE];

    for (int ct = 0; ct < NT/CHUNK; ct++){
        __syncthreads();
#pragma unroll
        for (int i = 0; i < 8; i++){
            int e = tid + i*256, r = e >> 2, seg = e & 3;
            *(uint4*)&sKV[r*SK_STRIDE + seg*8] =
                *(const uint4*)&gV[(size_t)(ct*CHUNK + r)*DH + seg*8];
        }
        __syncthreads();
#pragma unroll
        for (int kb = 0; kb < 4; kb++){
            int tc = wid*64 + kb*16;
            int colbase = ct*CHUNK + tc + 2*(lane & 3);
            unsigned afr[4];
#pragma unroll
            for (int cg = 0; cg < 2; cg++){
                int col = colbase + cg*8;
                __half2 pv = *(const __half2*)&srowA[col];
                float2 pf = __half22float2(pv);
                float2 o; o.x = pf.x*invA; o.y = pf.y*invA;
                *(float2*)&outA[col] = o;
                __half2 mh = *(const __half2*)&mrowA[col];
                __half2 t = __hmul2(__hmul2(pv, mh), invA2);
                afr[cg*2] = *reinterpret_cast<unsigned*>(&t);

                pv = *(const __half2*)&srowB[col];
                pf = __half22float2(pv);
                o.x = pf.x*invB; o.y = pf.y*invB;
                *(float2*)&outB[col] = o;
                mh = *(const __half2*)&mrowB[col];
                t = __hmul2(__hmul2(pv, mh), invB2);
                afr[cg*2 + 1] = *reinterpret_cast<unsigned*>(&t);
            }
#pragma unroll
            for (int nt = 0; nt < 4; nt++){
                uint32_t ba = s2u(&sKV[(tc + (lane & 15))*SK_STRIDE + nt*8]);
                unsigned b0, b1;
                ldsm_x2t(b0, b1, ba);
                mma16816(acc[nt], afr, b0, b1);
            }
        }
    }

    // ---- cross-warp AV reduction (reuse sKV region) ----
    __syncthreads();
    float* sRed = (float*)(smem + OFF_KV);   // 8 warps x 512 floats
#pragma unroll
    for (int nt = 0; nt < 4; nt++){
        int dd = nt*8 + 2*(lane & 3);
        float2 v0; v0.x = acc[nt][0]; v0.y = acc[nt][1];
        float2 v1; v1.x = acc[nt][2]; v1.y = acc[nt][3];
        *(float2*)&sRed[wid*512 + r_lo*32 + dd] = v0;
        *(float2*)&sRed[wid*512 + r_hi*32 + dd] = v1;
    }
    __syncthreads();
    for (int i = tid; i < 512; i += 256){
        float s = 0.f;
#pragma unroll
        for (int w = 0; w < 8; w++) s += sRed[w*512 + i];
        int qq = i >> 5, dd = i & 31;
        g_x[((size_t)b*NT + q0 + qq)*NC + h*DH + dd] = s;
    }
}

// ---------------- launch ----------------
extern "C" void kernel_launch(void* const* d_in, const int* in_sizes, int n_in,
                              void* d_out, int out_size)
{
    const float* query = (const float*)d_in[0];
    const float* mask  = (const float*)d_in[1];
    const float* Wq = (const float*)d_in[2]; const float* bq = (const float*)d_in[3];
    const float* Wk = (const float*)d_in[4]; const float* bk = (const float*)d_in[5];
    const float* Wv = (const float*)d_in[6]; const float* bv = (const float*)d_in[7];
    const float* Wo = (const float*)d_in[8]; const float* bo = (const float*)d_in[9];

    float* out_query = (float*)d_out;
    float* attn_vis  = out_query + (size_t)NB*NT*NC;

    cudaFuncSetAttribute(attn_kernel, cudaFuncAttributeMaxDynamicSharedMemorySize, SMEM_ATTN);

    colmax_part<<<dim3(NB, 64), 256>>>(mask);
    colmax_fin<<<NB*NT/256, 256>>>();
    gemm_kernel<false><<<dim3(NB*NT/128, NC/64, 3), 256>>>(
        query, Wq, bq, Wk, bk, Wv, bv, nullptr, nullptr);
    mask_prep_kernel<<<dim3(NT/32, NT/32, NB), 256>>>(mask);
    attn_kernel<<<dim3(NH, NT/TQ, NB), 256, SMEM_ATTN>>>(attn_vis);
    gemm_kernel<true><<<dim3(NB*NT/128, NC/64, 1), 256>>>(
        nullptr, Wo, bo, nullptr, nullptr, nullptr, nullptr, query, out_query);
}

// round 6
// speedup vs baseline: 1.1715x; 1.1715x over previous
#include <cuda_runtime.h>
#include <cuda_fp16.h>
#include <cstdint>

#define NB 4
#define NH 8
#define NT 2048
#define DH 32
#define NC 256
#define SCALE 0.17677669529663687f
#define L2E   1.4426950408889634f

static __device__ __half g_q[(size_t)NB*NH*NT*DH];
static __device__ __half g_k[(size_t)NB*NH*NT*DH];
static __device__ __half g_v[(size_t)NB*NH*NT*DH];
static __device__ float  g_x[(size_t)NB*NT*NC];
static __device__ float  g_icm[NB*NT];
static __device__ float  g_cmp[(size_t)NB*64*NT];
static __device__ __half g_mh[(size_t)NB*NT*NT];

__device__ __forceinline__ float fast_ex2(float x){
    float y; asm("ex2.approx.ftz.f32 %0, %1;" : "=f"(y) : "f"(x)); return y;
}
__device__ __forceinline__ void mma16816(float* c, const unsigned* a, unsigned b0, unsigned b1){
    asm volatile("mma.sync.aligned.m16n8k16.row.col.f32.f16.f16.f32 "
        "{%0,%1,%2,%3},{%4,%5,%6,%7},{%8,%9},{%0,%1,%2,%3};"
        : "+f"(c[0]), "+f"(c[1]), "+f"(c[2]), "+f"(c[3])
        : "r"(a[0]), "r"(a[1]), "r"(a[2]), "r"(a[3]), "r"(b0), "r"(b1));
}
__device__ __forceinline__ unsigned pack_half2(float x, float y){
    __half2 h = __floats2half2_rn(x, y); return *reinterpret_cast<unsigned*>(&h);
}
__device__ __forceinline__ uint32_t s2u(const void* p){
    return (uint32_t)__cvta_generic_to_shared(p);
}
__device__ __forceinline__ void ldsm_x4(unsigned* a, uint32_t addr){
    asm volatile("ldmatrix.sync.aligned.m8n8.x4.shared.b16 {%0,%1,%2,%3}, [%4];"
        : "=r"(a[0]),"=r"(a[1]),"=r"(a[2]),"=r"(a[3]) : "r"(addr));
}
__device__ __forceinline__ void ldsm_x2(unsigned& b0, unsigned& b1, uint32_t addr){
    asm volatile("ldmatrix.sync.aligned.m8n8.x2.shared.b16 {%0,%1}, [%2];"
        : "=r"(b0),"=r"(b1) : "r"(addr));
}
__device__ __forceinline__ void ldsm_x2t(unsigned& b0, unsigned& b1, uint32_t addr){
    asm volatile("ldmatrix.sync.aligned.m8n8.x2.trans.shared.b16 {%0,%1}, [%2];"
        : "=r"(b0),"=r"(b1) : "r"(addr));
}

// ---------------- mask prep (parallel) ----------------
__global__ void colmax_part(const float* __restrict__ mask){
    int b = blockIdx.x, s = blockIdx.y;
    const float* base = mask + (size_t)b*NT*NT + (size_t)s*32*NT;
#pragma unroll
    for (int qi = 0; qi < 8; qi++){
        int q = qi*256 + threadIdx.x;
        float mx = 0.f;
#pragma unroll
        for (int k = 0; k < 32; k++) mx = fmaxf(mx, base[(size_t)k*NT + q]);
        g_cmp[((size_t)b*64 + s)*NT + q] = mx;
    }
}
__global__ void colmax_fin(){
    int i = blockIdx.x*256 + threadIdx.x;
    int b = i >> 11, q = i & (NT-1);
    float mx = 0.f;
#pragma unroll
    for (int s = 0; s < 64; s++) mx = fmaxf(mx, g_cmp[((size_t)b*64 + s)*NT + q]);
    g_icm[i] = 1.0f / mx;
}

__global__ void mask_prep_kernel(const float* __restrict__ mask){
    __shared__ float t[32][33];
    int b = blockIdx.z;
    int k0 = blockIdx.x * 32, q0 = blockIdx.y * 32;
    int tx = threadIdx.x & 31, ty = threadIdx.x >> 5;
#pragma unroll
    for (int i = 0; i < 4; i++)
        t[ty + i*8][tx] = mask[(size_t)b*NT*NT + (size_t)(k0 + ty + i*8)*NT + q0 + tx];
    __syncthreads();
#pragma unroll
    for (int i = 0; i < 4; i++){
        int q = q0 + ty + i*8;
        g_mh[((size_t)b*NT + q)*NT + k0 + tx] =
            __float2half(t[tx][ty + i*8] * g_icm[b*NT + q]);
    }
}

// ---------------- GEMM: OUT[8192,256] = X @ W^T + bias ----------------
template<bool OUTPROJ>
__global__ __launch_bounds__(256) void gemm_kernel(
    const float* __restrict__ Xin,
    const float* __restrict__ Wa, const float* __restrict__ ba,
    const float* __restrict__ Wb, const float* __restrict__ bb_,
    const float* __restrict__ Wc, const float* __restrict__ bc,
    const float* __restrict__ resid, float* __restrict__ outF)
{
    __shared__ __half sA[128*72];
    __shared__ __half sB[64*72];
    const float* X = OUTPROJ ? (const float*)g_x : Xin;   // device-side symbol!
    const int m0 = blockIdx.x * 128, j0 = blockIdx.y * 64;
    const int pz = blockIdx.z;
    const float* W    = (pz == 0) ? Wa : (pz == 1) ? Wb : Wc;
    const float* bias = (pz == 0) ? ba : (pz == 1) ? bb_ : bc;
    __half* outH      = (pz == 0) ? g_q : (pz == 1) ? g_k : g_v;
    const float osc   = (!OUTPROJ && pz == 0) ? SCALE : 1.0f;

    const int tid = threadIdx.x, lane = tid & 31, wid = tid >> 5;
    const int wm = wid >> 1, wn = wid & 1;

    float acc[2][4][4];
#pragma unroll
    for (int m = 0; m < 2; m++)
#pragma unroll
        for (int nt = 0; nt < 4; nt++)
#pragma unroll
            for (int i = 0; i < 4; i++) acc[m][nt][i] = 0.f;

    for (int k0 = 0; k0 < NC; k0 += 64){
        __syncthreads();
#pragma unroll
        for (int i = 0; i < 8; i++){
            int e = tid + i*256, r = e >> 4, c4 = e & 15;
            float4 v = *(const float4*)&X[(size_t)(m0 + r)*NC + k0 + c4*4];
            *(__half2*)&sA[r*72 + c4*4]     = __floats2half2_rn(v.x, v.y);
            *(__half2*)&sA[r*72 + c4*4 + 2] = __floats2half2_rn(v.z, v.w);
        }
#pragma unroll
        for (int i = 0; i < 4; i++){
            int e = tid + i*256, r = e >> 4, c4 = e & 15;
            float4 v = *(const float4*)&W[(size_t)(j0 + r)*NC + k0 + c4*4];
            *(__half2*)&sB[r*72 + c4*4]     = __floats2half2_rn(v.x, v.y);
            *(__half2*)&sB[r*72 + c4*4 + 2] = __floats2half2_rn(v.z, v.w);
        }
        __syncthreads();
#pragma unroll
        for (int kk = 0; kk < 4; kk++){
            int dc = kk*16 + 2*(lane & 3);
            unsigned a[2][4], bb[4][2];
#pragma unroll
            for (int m = 0; m < 2; m++){
                int r = wm*32 + m*16 + (lane >> 2);
                a[m][0] = *(const unsigned*)&sA[r*72 + dc];
                a[m][1] = *(const unsigned*)&sA[(r + 8)*72 + dc];
                a[m][2] = *(const unsigned*)&sA[r*72 + dc + 8];
                a[m][3] = *(const unsigned*)&sA[(r + 8)*72 + dc + 8];
            }
#pragma unroll
            for (int nt = 0; nt < 4; nt++){
                int rj = wn*32 + nt*8 + (lane >> 2);
                bb[nt][0] = *(const unsigned*)&sB[rj*72 + dc];
                bb[nt][1] = *(const unsigned*)&sB[rj*72 + dc + 8];
            }
#pragma unroll
            for (int m = 0; m < 2; m++)
#pragma unroll
                for (int nt = 0; nt < 4; nt++)
                    mma16816(acc[m][nt], a[m], bb[nt][0], bb[nt][1]);
        }
    }

#pragma unroll
    for (int m = 0; m < 2; m++)
#pragma unroll
        for (int nt = 0; nt < 4; nt++){
            int row = m0 + wm*32 + m*16 + (lane >> 2);
            int col = j0 + wn*32 + nt*8 + 2*(lane & 3);
            float b0f = bias[col], b1f = bias[col + 1];
#pragma unroll
            for (int rg = 0; rg < 2; rg++){
                int rr = row + rg*8;
                if (OUTPROJ){
                    float2 o;
                    o.x = acc[m][nt][rg*2 + 0] + b0f + resid[(size_t)rr*NC + col];
                    o.y = acc[m][nt][rg*2 + 1] + b1f + resid[(size_t)rr*NC + col + 1];
                    *(float2*)&outF[(size_t)rr*NC + col] = o;
                } else {
                    int bb2 = rr >> 11, n = rr & (NT-1);
                    int hh = col >> 5, dd = col & 31;
                    size_t addr = ((size_t)(bb2*NH + hh)*NT + n)*DH + dd;
                    *(__half2*)&outH[addr] =
                        __floats2half2_rn((acc[m][nt][rg*2 + 0] + b0f)*osc,
                                          (acc[m][nt][rg*2 + 1] + b1f)*osc);
                }
            }
        }
}

// ---------------- fused attention (TQ=16, 2 CTAs/SM) ----------------
#define TQ 16
#define CHUNK 512
#define SS_STRIDE 2056
#define SK_STRIDE 40
#define OFF_S   0
#define SZ_S    (TQ*SS_STRIDE*2)             // 65792
#define OFF_KV  (SZ_S)
#define SZ_KV   (CHUNK*SK_STRIDE*2)          // 40960
#define OFF_Q   (OFF_KV + SZ_KV)             // 106752
#define SZ_Q    (TQ*SK_STRIDE*2)             // 1280
#define SMEM_ATTN (OFF_Q + SZ_Q + 64)        // ~108KB -> 2 CTAs/SM

__global__ __launch_bounds__(256, 2) void attn_kernel(float* __restrict__ attn_out)
{
    extern __shared__ char smem[];
    __half* sS  = (__half*)(smem + OFF_S);
    __half* sKV = (__half*)(smem + OFF_KV);
    __half* sQ  = (__half*)(smem + OFF_Q);

    const int h = blockIdx.x, qt = blockIdx.y, b = blockIdx.z;
    const int bh = b*NH + h;
    const int q0 = qt*TQ;
    const int tid = threadIdx.x, lane = tid & 31, wid = tid >> 5;

    const __half* gQ = g_q + ((size_t)bh*NT + q0)*DH;
    const __half* gK = g_k + (size_t)bh*NT*DH;
    const __half* gV = g_v + (size_t)bh*NT*DH;

    if (tid < 64){
        int r = tid >> 2, seg = tid & 3;
        *(uint4*)&sQ[r*SK_STRIDE + seg*8] = *(const uint4*)&gQ[r*DH + seg*8];
    }

    // ---- Phase 1: E = exp(Q K^T) -> smem half (Q pre-scaled; exp fused) ----
    unsigned aq[2][4];
    for (int ct = 0; ct < NT/CHUNK; ct++){
        __syncthreads();
#pragma unroll
        for (int i = 0; i < 8; i++){
            int e = tid + i*256, r = e >> 2, seg = e & 3;
            *(uint4*)&sKV[r*SK_STRIDE + seg*8] =
                *(const uint4*)&gK[(size_t)(ct*CHUNK + r)*DH + seg*8];
        }
        __syncthreads();
        if (ct == 0){
            uint32_t qa0 = s2u(&sQ[(lane & 15)*SK_STRIDE + 8*(lane >> 4)]);
            ldsm_x4(aq[0], qa0);
            ldsm_x4(aq[1], qa0 + 32);   // k 16..31
        }
#pragma unroll
        for (int nt = 0; nt < 8; nt++){
            int t0 = wid*64 + nt*8;
            uint32_t ba = s2u(&sKV[(t0 + (lane & 7))*SK_STRIDE + 8*((lane >> 3) & 1)]);
            float c[4] = {0.f,0.f,0.f,0.f};
            unsigned b0, b1;
            ldsm_x2(b0, b1, ba);
            mma16816(c, aq[0], b0, b1);
            ldsm_x2(b0, b1, ba + 32);
            mma16816(c, aq[1], b0, b1);
            float e0 = fast_ex2(c[0]*L2E), e1 = fast_ex2(c[1]*L2E);
            float e2 = fast_ex2(c[2]*L2E), e3 = fast_ex2(c[3]*L2E);
            int gc = ct*CHUNK + t0 + 2*(lane & 3);
            int r0 = lane >> 2;
            *(__half2*)&sS[(r0    )*SS_STRIDE + gc] = __floats2half2_rn(e0, e1);
            *(__half2*)&sS[(r0 + 8)*SS_STRIDE + gc] = __floats2half2_rn(e2, e3);
        }
    }
    __syncthreads();

    // ---- Phase 2 (per-warp, no CTA sync): row sum -> inv; then vectorized
    //      normalize: attn_vis STG.128 and masked probs back into sS ----
#pragma unroll
    for (int rr = 0; rr < 2; rr++){
        int row = wid*2 + rr;
        __half* srow = &sS[row*SS_STRIDE];
        float sum = 0.f;
#pragma unroll 2
        for (int j = lane; j < NT/8; j += 32){
            uint4 u = *(uint4*)&srow[j*8];
            float2 f0 = __half22float2(*(__half2*)&u.x);
            float2 f1 = __half22float2(*(__half2*)&u.y);
            float2 f2 = __half22float2(*(__half2*)&u.z);
            float2 f3 = __half22float2(*(__half2*)&u.w);
            sum += ((f0.x + f0.y) + (f1.x + f1.y)) + ((f2.x + f2.y) + (f3.x + f3.y));
        }
#pragma unroll
        for (int o = 16; o > 0; o >>= 1) sum += __shfl_xor_sync(0xffffffffu, sum, o);
        const float inv = 1.0f / sum;
        const __half2 inv2 = __float2half2_rn(inv);
        const __half* mrow = g_mh + ((size_t)b*NT + q0 + row)*NT;
        float* orow = attn_out + ((size_t)bh*NT + q0 + row)*NT;
#pragma unroll 2
        for (int j = lane; j < NT/8; j += 32){
            uint4 u = *(uint4*)&srow[j*8];
            uint4 mu = *(const uint4*)&mrow[j*8];
            __half2 e0 = *(__half2*)&u.x, e1 = *(__half2*)&u.y;
            __half2 e2 = *(__half2*)&u.z, e3 = *(__half2*)&u.w;
            float2 f0 = __half22float2(e0), f1 = __half22float2(e1);
            float2 f2 = __half22float2(e2), f3 = __half22float2(e3);
            float4 v0, v1;
            v0.x = f0.x*inv; v0.y = f0.y*inv; v0.z = f1.x*inv; v0.w = f1.y*inv;
            v1.x = f2.x*inv; v1.y = f2.y*inv; v1.z = f3.x*inv; v1.w = f3.y*inv;
            *(float4*)&orow[j*8]     = v0;
            *(float4*)&orow[j*8 + 4] = v1;
            __half2 p0 = __hmul2(__hmul2(e0, *(__half2*)&mu.x), inv2);
            __half2 p1 = __hmul2(__hmul2(e1, *(__half2*)&mu.y), inv2);
            __half2 p2 = __hmul2(__hmul2(e2, *(__half2*)&mu.z), inv2);
            __half2 p3 = __hmul2(__hmul2(e3, *(__half2*)&mu.w), inv2);
            uint4 w;
            w.x = *reinterpret_cast<unsigned*>(&p0);
            w.y = *reinterpret_cast<unsigned*>(&p1);
            w.z = *reinterpret_cast<unsigned*>(&p2);
            w.w = *reinterpret_cast<unsigned*>(&p3);
            *(uint4*)&srow[j*8] = w;
        }
    }

    // ---- Phase 3: pure MMA — A = masked probs (sS), B = V ----
    float acc[4][4];
#pragma unroll
    for (int nt = 0; nt < 4; nt++)
#pragma unroll
        for (int i = 0; i < 4; i++) acc[nt][i] = 0.f;

    for (int ct = 0; ct < NT/CHUNK; ct++){
        __syncthreads();
#pragma unroll
        for (int i = 0; i < 8; i++){
            int e = tid + i*256, r = e >> 2, seg = e & 3;
            *(uint4*)&sKV[r*SK_STRIDE + seg*8] =
                *(const uint4*)&gV[(size_t)(ct*CHUNK + r)*DH + seg*8];
        }
        __syncthreads();
#pragma unroll
        for (int kb = 0; kb < 4; kb++){
            int tc = wid*64 + kb*16;
            int gcol = ct*CHUNK + tc;
            unsigned a[4];
            ldsm_x4(a, s2u(&sS[(lane & 15)*SS_STRIDE + gcol + 8*(lane >> 4)]));
#pragma unroll
            for (int nt = 0; nt < 4; nt++){
                unsigned b0, b1;
                ldsm_x2t(b0, b1, s2u(&sKV[(tc + (lane & 15))*SK_STRIDE + nt*8]));
                mma16816(acc[nt], a, b0, b1);
            }
        }
    }

    // ---- cross-warp AV reduction (reuse sKV region) ----
    __syncthreads();
    const int r_lo = lane >> 2, r_hi = r_lo + 8;
    float* sRed = (float*)(smem + OFF_KV);   // 8 warps x 512 floats
#pragma unroll
    for (int nt = 0; nt < 4; nt++){
        int dd = nt*8 + 2*(lane & 3);
        float2 v0; v0.x = acc[nt][0]; v0.y = acc[nt][1];
        float2 v1; v1.x = acc[nt][2]; v1.y = acc[nt][3];
        *(float2*)&sRed[wid*512 + r_lo*32 + dd] = v0;
        *(float2*)&sRed[wid*512 + r_hi*32 + dd] = v1;
    }
    __syncthreads();
    for (int i = tid; i < 512; i += 256){
        float s = 0.f;
#pragma unroll
        for (int w = 0; w < 8; w++) s += sRed[w*512 + i];
        int qq = i >> 5, dd = i & 31;
        g_x[((size_t)b*NT + q0 + qq)*NC + h*DH + dd] = s;
    }
}

// ---------------- launch ----------------
extern "C" void kernel_launch(void* const* d_in, const int* in_sizes, int n_in,
                              void* d_out, int out_size)
{
    const float* query = (const float*)d_in[0];
    const float* mask  = (const float*)d_in[1];
    const float* Wq = (const float*)d_in[2]; const float* bq = (const float*)d_in[3];
    const float* Wk = (const float*)d_in[4]; const float* bk = (const float*)d_in[5];
    const float* Wv = (const float*)d_in[6]; const float* bv = (const float*)d_in[7];
    const float* Wo = (const float*)d_in[8]; const float* bo = (const float*)d_in[9];

    float* out_query = (float*)d_out;
    float* attn_vis  = out_query + (size_t)NB*NT*NC;

    cudaFuncSetAttribute(attn_kernel, cudaFuncAttributeMaxDynamicSharedMemorySize, SMEM_ATTN);

    colmax_part<<<dim3(NB, 64), 256>>>(mask);
    colmax_fin<<<NB*NT/256, 256>>>();
    gemm_kernel<false><<<dim3(NB*NT/128, NC/64, 3), 256>>>(
        query, Wq, bq, Wk, bk, Wv, bv, nullptr, nullptr);
    mask_prep_kernel<<<dim3(NT/32, NT/32, NB), 256>>>(mask);
    attn_kernel<<<dim3(NH, NT/TQ, NB), 256, SMEM_ATTN>>>(attn_vis);
    gemm_kernel<true><<<dim3(NB*NT/128, NC/64, 1), 256>>>(
        nullptr, Wo, bo, nullptr, nullptr, nullptr, nullptr, query, out_query);
}

// round 7
// speedup vs baseline: 1.2510x; 1.0679x over previous
#include <cuda_runtime.h>
#include <cuda_fp16.h>
#include <cstdint>

#define NB 4
#define NH 8
#define NT 2048
#define DH 32
#define NC 256
#define SCALE 0.17677669529663687f
#define L2E   1.4426950408889634f

static __device__ __half g_q[(size_t)NB*NH*NT*DH];
static __device__ __half g_k[(size_t)NB*NH*NT*DH];
static __device__ __half g_v[(size_t)NB*NH*NT*DH];
static __device__ float  g_x[(size_t)NB*NT*NC];
static __device__ float  g_icm[NB*NT];
static __device__ float  g_cmp[(size_t)NB*64*NT];
static __device__ __half g_mh[(size_t)NB*NT*NT];   // transposed, UNnormalized

__device__ __forceinline__ float fast_ex2(float x){
    float y; asm("ex2.approx.ftz.f32 %0, %1;" : "=f"(y) : "f"(x)); return y;
}
__device__ __forceinline__ void mma16816(float* c, const unsigned* a, unsigned b0, unsigned b1){
    asm volatile("mma.sync.aligned.m16n8k16.row.col.f32.f16.f16.f32 "
        "{%0,%1,%2,%3},{%4,%5,%6,%7},{%8,%9},{%0,%1,%2,%3};"
        : "+f"(c[0]), "+f"(c[1]), "+f"(c[2]), "+f"(c[3])
        : "r"(a[0]), "r"(a[1]), "r"(a[2]), "r"(a[3]), "r"(b0), "r"(b1));
}
__device__ __forceinline__ uint32_t s2u(const void* p){
    return (uint32_t)__cvta_generic_to_shared(p);
}
__device__ __forceinline__ void ldsm_x4(unsigned* a, uint32_t addr){
    asm volatile("ldmatrix.sync.aligned.m8n8.x4.shared.b16 {%0,%1,%2,%3}, [%4];"
        : "=r"(a[0]),"=r"(a[1]),"=r"(a[2]),"=r"(a[3]) : "r"(addr));
}
__device__ __forceinline__ void ldsm_x2(unsigned& b0, unsigned& b1, uint32_t addr){
    asm volatile("ldmatrix.sync.aligned.m8n8.x2.shared.b16 {%0,%1}, [%2];"
        : "=r"(b0),"=r"(b1) : "r"(addr));
}
__device__ __forceinline__ void ldsm_x2t(unsigned& b0, unsigned& b1, uint32_t addr){
    asm volatile("ldmatrix.sync.aligned.m8n8.x2.trans.shared.b16 {%0,%1}, [%2];"
        : "=r"(b0),"=r"(b1) : "r"(addr));
}
#define CPA16(dst, src) asm volatile("cp.async.cg.shared.global [%0], [%1], 16;" :: "r"(dst), "l"(src))
#define CPA_COMMIT() asm volatile("cp.async.commit_group;")
#define CPA_WAIT()   asm volatile("cp.async.wait_group 0;" ::: "memory")

// ---------------- fused mask transpose + column-max partials ----------------
// writes g_mh[b][q][k] = half(mask[b][k][q])  (unnormalized)
// and    g_cmp[b][k0/32][q] = max over 32 k's of mask[b][k][q]
__global__ void mask_prep_kernel(const float* __restrict__ mask){
    __shared__ float t[32][33];
    __shared__ float pm[8][32];
    int b = blockIdx.z;
    int k0 = blockIdx.x * 32, q0 = blockIdx.y * 32;
    int tx = threadIdx.x & 31, ty = threadIdx.x >> 5;
#pragma unroll
    for (int i = 0; i < 4; i++)
        t[ty + i*8][tx] = mask[(size_t)b*NT*NT + (size_t)(k0 + ty + i*8)*NT + q0 + tx];
    __syncthreads();
#pragma unroll
    for (int i = 0; i < 4; i++){
        int q = q0 + ty + i*8;
        g_mh[((size_t)b*NT + q)*NT + k0 + tx] = __float2half(t[tx][ty + i*8]);
    }
    float m2 = 0.f;
#pragma unroll
    for (int j = 0; j < 4; j++) m2 = fmaxf(m2, t[ty*4 + j][tx]);
    pm[ty][tx] = m2;
    __syncthreads();
    if (ty == 0){
        float m3 = pm[0][tx];
#pragma unroll
        for (int w = 1; w < 8; w++) m3 = fmaxf(m3, pm[w][tx]);
        g_cmp[((size_t)b*64 + (k0 >> 5))*NT + q0 + tx] = m3;
    }
}
__global__ void colmax_fin(){
    int i = blockIdx.x*256 + threadIdx.x;
    int b = i >> 11, q = i & (NT-1);
    float mx = 0.f;
#pragma unroll
    for (int s = 0; s < 64; s++) mx = fmaxf(mx, g_cmp[((size_t)b*64 + s)*NT + q]);
    g_icm[i] = 1.0f / mx;
}

// ---------------- GEMM: OUT[8192,256] = X @ W^T + bias ----------------
template<bool OUTPROJ>
__global__ __launch_bounds__(256) void gemm_kernel(
    const float* __restrict__ Xin,
    const float* __restrict__ Wa, const float* __restrict__ ba,
    const float* __restrict__ Wb, const float* __restrict__ bb_,
    const float* __restrict__ Wc, const float* __restrict__ bc,
    const float* __restrict__ resid, float* __restrict__ outF)
{
    __shared__ __half sA[128*72];
    __shared__ __half sB[64*72];
    const float* X = OUTPROJ ? (const float*)g_x : Xin;   // device-side symbol!
    const int m0 = blockIdx.x * 128, j0 = blockIdx.y * 64;
    const int pz = blockIdx.z;
    const float* W    = (pz == 0) ? Wa : (pz == 1) ? Wb : Wc;
    const float* bias = (pz == 0) ? ba : (pz == 1) ? bb_ : bc;
    __half* outH      = (pz == 0) ? g_q : (pz == 1) ? g_k : g_v;
    const float osc   = (!OUTPROJ && pz == 0) ? SCALE : 1.0f;

    const int tid = threadIdx.x, lane = tid & 31, wid = tid >> 5;
    const int wm = wid >> 1, wn = wid & 1;

    float acc[2][4][4];
#pragma unroll
    for (int m = 0; m < 2; m++)
#pragma unroll
        for (int nt = 0; nt < 4; nt++)
#pragma unroll
            for (int i = 0; i < 4; i++) acc[m][nt][i] = 0.f;

    for (int k0 = 0; k0 < NC; k0 += 64){
        __syncthreads();
#pragma unroll
        for (int i = 0; i < 8; i++){
            int e = tid + i*256, r = e >> 4, c4 = e & 15;
            float4 v = *(const float4*)&X[(size_t)(m0 + r)*NC + k0 + c4*4];
            *(__half2*)&sA[r*72 + c4*4]     = __floats2half2_rn(v.x, v.y);
            *(__half2*)&sA[r*72 + c4*4 + 2] = __floats2half2_rn(v.z, v.w);
        }
#pragma unroll
        for (int i = 0; i < 4; i++){
            int e = tid + i*256, r = e >> 4, c4 = e & 15;
            float4 v = *(const float4*)&W[(size_t)(j0 + r)*NC + k0 + c4*4];
            *(__half2*)&sB[r*72 + c4*4]     = __floats2half2_rn(v.x, v.y);
            *(__half2*)&sB[r*72 + c4*4 + 2] = __floats2half2_rn(v.z, v.w);
        }
        __syncthreads();
#pragma unroll
        for (int kk = 0; kk < 4; kk++){
            int dc = kk*16 + 2*(lane & 3);
            unsigned a[2][4], bb[4][2];
#pragma unroll
            for (int m = 0; m < 2; m++){
                int r = wm*32 + m*16 + (lane >> 2);
                a[m][0] = *(const unsigned*)&sA[r*72 + dc];
                a[m][1] = *(const unsigned*)&sA[(r + 8)*72 + dc];
                a[m][2] = *(const unsigned*)&sA[r*72 + dc + 8];
                a[m][3] = *(const unsigned*)&sA[(r + 8)*72 + dc + 8];
            }
#pragma unroll
            for (int nt = 0; nt < 4; nt++){
                int rj = wn*32 + nt*8 + (lane >> 2);
                bb[nt][0] = *(const unsigned*)&sB[rj*72 + dc];
                bb[nt][1] = *(const unsigned*)&sB[rj*72 + dc + 8];
            }
#pragma unroll
            for (int m = 0; m < 2; m++)
#pragma unroll
                for (int nt = 0; nt < 4; nt++)
                    mma16816(acc[m][nt], a[m], bb[nt][0], bb[nt][1]);
        }
    }

#pragma unroll
    for (int m = 0; m < 2; m++)
#pragma unroll
        for (int nt = 0; nt < 4; nt++){
            int row = m0 + wm*32 + m*16 + (lane >> 2);
            int col = j0 + wn*32 + nt*8 + 2*(lane & 3);
            float b0f = bias[col], b1f = bias[col + 1];
#pragma unroll
            for (int rg = 0; rg < 2; rg++){
                int rr = row + rg*8;
                if (OUTPROJ){
                    float2 o;
                    o.x = acc[m][nt][rg*2 + 0] + b0f + resid[(size_t)rr*NC + col];
                    o.y = acc[m][nt][rg*2 + 1] + b1f + resid[(size_t)rr*NC + col + 1];
                    *(float2*)&outF[(size_t)rr*NC + col] = o;
                } else {
                    int bb2 = rr >> 11, n = rr & (NT-1);
                    int hh = col >> 5, dd = col & 31;
                    size_t addr = ((size_t)(bb2*NH + hh)*NT + n)*DH + dd;
                    *(__half2*)&outH[addr] =
                        __floats2half2_rn((acc[m][nt][rg*2 + 0] + b0f)*osc,
                                          (acc[m][nt][rg*2 + 1] + b1f)*osc);
                }
            }
        }
}

// ---------------- fused attention (TQ=16, 2 CTAs/SM) ----------------
#define TQ 16
#define CHUNK 512
#define SS_STRIDE 2056
#define SK_STRIDE 40
#define OFF_S   0
#define SZ_S    (TQ*SS_STRIDE*2)             // 65792
#define OFF_KV  (SZ_S)
#define SZ_KV   (CHUNK*SK_STRIDE*2)          // 40960
#define OFF_Q   (OFF_KV + SZ_KV)             // 106752
#define SZ_Q    (TQ*SK_STRIDE*2)             // 1280
#define OFF_SUM (OFF_Q + SZ_Q)               // 108032
#define SMEM_ATTN (OFF_SUM + 8*16*4)         // 108544 -> 2 CTAs/SM

__global__ __launch_bounds__(256, 2) void attn_kernel(float* __restrict__ attn_out)
{
    extern __shared__ char smem[];
    __half* sS   = (__half*)(smem + OFF_S);
    __half* sKV  = (__half*)(smem + OFF_KV);
    __half* sQ   = (__half*)(smem + OFF_Q);
    float*  sSum = (float*)(smem + OFF_SUM);

    const int h = blockIdx.x, qt = blockIdx.y, b = blockIdx.z;
    const int bh = b*NH + h;
    const int q0 = qt*TQ;
    const int tid = threadIdx.x, lane = tid & 31, wid = tid >> 5;

    const __half* gQ = g_q + ((size_t)bh*NT + q0)*DH;
    const __half* gK = g_k + (size_t)bh*NT*DH;
    const __half* gV = g_v + (size_t)bh*NT*DH;

    if (tid < 64){
        int r = tid >> 2, seg = tid & 3;
        *(uint4*)&sQ[r*SK_STRIDE + seg*8] = *(const uint4*)&gQ[r*DH + seg*8];
    }

    // ---- Phase 1: E = exp(Q K^T) -> smem half; row-sum partials in regs ----
    unsigned aq[2][4];
    float sum_lo = 0.f, sum_hi = 0.f;
    for (int ct = 0; ct < NT/CHUNK; ct++){
        __syncthreads();
#pragma unroll
        for (int i = 0; i < 8; i++){
            int e = tid + i*256, r = e >> 2, seg = e & 3;
            CPA16(s2u(&sKV[r*SK_STRIDE + seg*8]),
                  &gK[(size_t)(ct*CHUNK + r)*DH + seg*8]);
        }
        CPA_COMMIT();
        CPA_WAIT();
        __syncthreads();
        if (ct == 0){
            uint32_t qa0 = s2u(&sQ[(lane & 15)*SK_STRIDE + 8*(lane >> 4)]);
            ldsm_x4(aq[0], qa0);
            ldsm_x4(aq[1], qa0 + 32);   // k 16..31
        }
#pragma unroll
        for (int nt = 0; nt < 8; nt++){
            int t0 = wid*64 + nt*8;
            uint32_t ba = s2u(&sKV[(t0 + (lane & 7))*SK_STRIDE + 8*((lane >> 3) & 1)]);
            float c[4] = {0.f,0.f,0.f,0.f};
            unsigned b0, b1;
            ldsm_x2(b0, b1, ba);
            mma16816(c, aq[0], b0, b1);
            ldsm_x2(b0, b1, ba + 32);
            mma16816(c, aq[1], b0, b1);
            float e0 = fast_ex2(c[0]*L2E), e1 = fast_ex2(c[1]*L2E);
            float e2 = fast_ex2(c[2]*L2E), e3 = fast_ex2(c[3]*L2E);
            sum_lo += e0 + e1;
            sum_hi += e2 + e3;
            int gc = ct*CHUNK + t0 + 2*(lane & 3);
            int r0 = lane >> 2;
            *(__half2*)&sS[(r0    )*SS_STRIDE + gc] = __floats2half2_rn(e0, e1);
            *(__half2*)&sS[(r0 + 8)*SS_STRIDE + gc] = __floats2half2_rn(e2, e3);
        }
    }
    // reduce row partials across the 4 lanes sharing a row, stage per warp
    sum_lo += __shfl_xor_sync(0xffffffffu, sum_lo, 1);
    sum_lo += __shfl_xor_sync(0xffffffffu, sum_lo, 2);
    sum_hi += __shfl_xor_sync(0xffffffffu, sum_hi, 1);
    sum_hi += __shfl_xor_sync(0xffffffffu, sum_hi, 2);
    if ((lane & 3) == 0){
        sSum[wid*16 + (lane >> 2)]     = sum_lo;
        sSum[wid*16 + (lane >> 2) + 8] = sum_hi;
    }
    __syncthreads();

    // ---- Phase 2 (per-warp): inv from staged partials; vectorized normalize:
    //      attn_vis STG.128 and masked probs (x icm) back into sS ----
#pragma unroll
    for (int rr = 0; rr < 2; rr++){
        int row = wid*2 + rr;
        __half* srow = &sS[row*SS_STRIDE];
        float sum = 0.f;
#pragma unroll
        for (int w = 0; w < 8; w++) sum += sSum[w*16 + row];
        const float inv = 1.0f / sum;
        const __half2 inv2 = __float2half2_rn(inv * g_icm[b*NT + q0 + row]);
        const __half* mrow = g_mh + ((size_t)b*NT + q0 + row)*NT;
        float* orow = attn_out + ((size_t)bh*NT + q0 + row)*NT;
#pragma unroll 2
        for (int j = lane; j < NT/8; j += 32){
            uint4 u = *(uint4*)&srow[j*8];
            uint4 mu = *(const uint4*)&mrow[j*8];
            __half2 e0 = *(__half2*)&u.x, e1 = *(__half2*)&u.y;
            __half2 e2 = *(__half2*)&u.z, e3 = *(__half2*)&u.w;
            float2 f0 = __half22float2(e0), f1 = __half22float2(e1);
            float2 f2 = __half22float2(e2), f3 = __half22float2(e3);
            float4 v0, v1;
            v0.x = f0.x*inv; v0.y = f0.y*inv; v0.z = f1.x*inv; v0.w = f1.y*inv;
            v1.x = f2.x*inv; v1.y = f2.y*inv; v1.z = f3.x*inv; v1.w = f3.y*inv;
            *(float4*)&orow[j*8]     = v0;
            *(float4*)&orow[j*8 + 4] = v1;
            __half2 p0 = __hmul2(__hmul2(e0, *(__half2*)&mu.x), inv2);
            __half2 p1 = __hmul2(__hmul2(e1, *(__half2*)&mu.y), inv2);
            __half2 p2 = __hmul2(__hmul2(e2, *(__half2*)&mu.z), inv2);
            __half2 p3 = __hmul2(__hmul2(e3, *(__half2*)&mu.w), inv2);
            uint4 w;
            w.x = *reinterpret_cast<unsigned*>(&p0);
            w.y = *reinterpret_cast<unsigned*>(&p1);
            w.z = *reinterpret_cast<unsigned*>(&p2);
            w.w = *reinterpret_cast<unsigned*>(&p3);
            *(uint4*)&srow[j*8] = w;
        }
    }

    // ---- Phase 3: pure MMA — A = masked probs (sS), B = V ----
    float acc[4][4];
#pragma unroll
    for (int nt = 0; nt < 4; nt++)
#pragma unroll
        for (int i = 0; i < 4; i++) acc[nt][i] = 0.f;

    for (int ct = 0; ct < NT/CHUNK; ct++){
        __syncthreads();
#pragma unroll
        for (int i = 0; i < 8; i++){
            int e = tid + i*256, r = e >> 2, seg = e & 3;
            CPA16(s2u(&sKV[r*SK_STRIDE + seg*8]),
                  &gV[(size_t)(ct*CHUNK + r)*DH + seg*8]);
        }
        CPA_COMMIT();
        CPA_WAIT();
        __syncthreads();
#pragma unroll
        for (int kb = 0; kb < 4; kb++){
            int tc = wid*64 + kb*16;
            int gcol = ct*CHUNK + tc;
            unsigned a[4];
            ldsm_x4(a, s2u(&sS[(lane & 15)*SS_STRIDE + gcol + 8*(lane >> 4)]));
#pragma unroll
            for (int nt = 0; nt < 4; nt++){
                unsigned b0, b1;
                ldsm_x2t(b0, b1, s2u(&sKV[(tc + (lane & 15))*SK_STRIDE + nt*8]));
                mma16816(acc[nt], a, b0, b1);
            }
        }
    }

    // ---- cross-warp AV reduction (reuse sKV region) ----
    __syncthreads();
    const int r_lo = lane >> 2, r_hi = r_lo + 8;
    float* sRed = (float*)(smem + OFF_KV);   // 8 warps x 512 floats
#pragma unroll
    for (int nt = 0; nt < 4; nt++){
        int dd = nt*8 + 2*(lane & 3);
        float2 v0; v0.x = acc[nt][0]; v0.y = acc[nt][1];
        float2 v1; v1.x = acc[nt][2]; v1.y = acc[nt][3];
        *(float2*)&sRed[wid*512 + r_lo*32 + dd] = v0;
        *(float2*)&sRed[wid*512 + r_hi*32 + dd] = v1;
    }
    __syncthreads();
    for (int i = tid; i < 512; i += 256){
        float s = 0.f;
#pragma unroll
        for (int w = 0; w < 8; w++) s += sRed[w*512 + i];
        int qq = i >> 5, dd = i & 31;
        g_x[((size_t)b*NT + q0 + qq)*NC + h*DH + dd] = s;
    }
}

// ---------------- launch ----------------
extern "C" void kernel_launch(void* const* d_in, const int* in_sizes, int n_in,
                              void* d_out, int out_size)
{
    const float* query = (const float*)d_in[0];
    const float* mask  = (const float*)d_in[1];
    const float* Wq = (const float*)d_in[2]; const float* bq = (const float*)d_in[3];
    const float* Wk = (const float*)d_in[4]; const float* bk = (const float*)d_in[5];
    const float* Wv = (const float*)d_in[6]; const float* bv = (const float*)d_in[7];
    const float* Wo = (const float*)d_in[8]; const float* bo = (const float*)d_in[9];

    float* out_query = (float*)d_out;
    float* attn_vis  = out_query + (size_t)NB*NT*NC;

    cudaFuncSetAttribute(attn_kernel, cudaFuncAttributeMaxDynamicSharedMemorySize, SMEM_ATTN);

    mask_prep_kernel<<<dim3(NT/32, NT/32, NB), 256>>>(mask);
    colmax_fin<<<NB*NT/256, 256>>>();
    gemm_kernel<false><<<dim3(NB*NT/128, NC/64, 3), 256>>>(
        query, Wq, bq, Wk, bk, Wv, bv, nullptr, nullptr);
    attn_kernel<<<dim3(NH, NT/TQ, NB), 256, SMEM_ATTN>>>(attn_vis);
    gemm_kernel<true><<<dim3(NB*NT/128, NC/64, 1), 256>>>(
        nullptr, Wo, bo, nullptr, nullptr, nullptr, nullptr, query, out_query);
}